// round 10
// baseline (speedup 1.0000x reference)
#include <cuda_runtime.h>
#include <math.h>
#include <stdint.h>

#define NN    8192
#define DD    512
#define NBAGS 64
#define BAG   128
#define TOPK  16

#define CORR_JOBS (2 * NBAGS)           // 128 jobs: (bag, row-half) 64x128 tiles
#define XW_JOBS   ((NN / 64) * (DD / 128)) // 512 jobs: 64x128 xw tiles
#define NJOBS     (CORR_JOBS + XW_JOBS)   // 640
#define GRID_A    296                     // 148 SMs x 2 CTAs

// ---- scratch (static device globals: no allocation at runtime) ----
static __device__ float g_corr[NBAGS * BAG * BAG]; // per-bag cosine blocks (4 MB)
static __device__ float g_xw[NN * DD];             // features @ W (16 MB)
static __device__ float g_w[NN];                   // per-row GCN weight
static __device__ int   g_jobctr;                  // dynamic job counter

// packed fp32x2 FMA (Blackwell FFMA2; only reachable via PTX)
#define FMA2(c, a, b) \
    asm("fma.rn.f32x2 %0, %1, %2, %0;" : "+l"(c) : "l"(a), "l"(b))
#define D2L(x) __double_as_longlong(x)
#define LOF(u) __uint_as_float((unsigned)(u))
#define HIF(u) __uint_as_float((unsigned)((u) >> 32))

// ---------------------------------------------------------------------------
// Kernel A: zero-fill output + 640 uniform 64x128 GEMM jobs via work-stealing.
//   job <  128 : corr half-tile (bag g, rows h*64..h*64+63) x all 128 bag rows,
//                col norms accumulated in-loop, normalized output -> g_corr
//   job >= 128 : xw tile (64 rows of features) @ (128 cols of W) -> g_xw
// Math: packed f32x2 FMA; A-operand duplicated in smem so pairs load free.
// ---------------------------------------------------------------------------
__global__ __launch_bounds__(256, 2) void fused_A(const float* __restrict__ F,
                                                  const float* __restrict__ W,
                                                  float4* __restrict__ outz,
                                                  int total4) {
    __shared__ double As[2][16 * 66];     // duplicated a-pairs: 66 doubles/row-of-k
    __shared__ float  Bs[2][16 * 128];
    __shared__ float  ss_part[2][128];
    __shared__ float  ninv_s[128];
    __shared__ int    job_s;
    int tid = threadIdx.x;

    // ---- zero-fill slice of d_out (stores drain under compute) ----
    {
        float4 z = make_float4(0.f, 0.f, 0.f, 0.f);
        for (size_t i = (size_t)blockIdx.x * 256 + tid; i < (size_t)total4;
             i += (size_t)GRID_A * 256)
            outz[i] = z;
    }

    int tx  = tid & 15, ty = tid >> 4;     // math: 4 rows x 8 cols per thread
    int ar  = tid >> 2, ak = (tid & 3) << 2;   // A staging
    int bkr = tid >> 5, bn = (tid & 31) << 2;  // B staging (xw, natural)
    int cj  = tid & 127, ckg = tid >> 7;       // B staging (corr, transposed)

    for (;;) {
        __syncthreads();                   // protects smem reuse across jobs
        if (tid == 0) job_s = atomicAdd(&g_jobctr, 1);
        __syncthreads();
        int job = job_s;
        if (job >= NJOBS) break;

        bool iscorr = job < CORR_JOBS;
        const float* Ab; const float* Bb;
        int g = 0, h = 0, m0 = 0, n0 = 0;
        if (iscorr) {
            g = job >> 1; h = job & 1;
            Ab = F + ((size_t)(g * BAG + h * 64)) * DD;
            Bb = F + ((size_t)g * BAG) * DD;
        } else {
            int t = job - CORR_JOBS;
            m0 = (t >> 2) * 64; n0 = (t & 3) * 128;
            Ab = F + (size_t)m0 * DD;
            Bb = W;
        }

        unsigned long long acc[4][4];
#pragma unroll
        for (int i = 0; i < 4; i++)
#pragma unroll
            for (int j = 0; j < 4; j++) acc[i][j] = 0ull;
        float np = 0.f;

        // prefetch k-tile 0
        float4 ra = *(const float4*)(Ab + (size_t)ar * DD + ak);
        float4 rb0, rb1;
        if (iscorr) {
            rb0 = *(const float4*)(Bb + (size_t)cj * DD + ckg * 4);
            rb1 = *(const float4*)(Bb + (size_t)cj * DD + ckg * 4 + 8);
        } else {
            rb0 = *(const float4*)(Bb + (size_t)bkr * DD + n0 + bn);
            rb1 = *(const float4*)(Bb + (size_t)(bkr + 8) * DD + n0 + bn);
        }

        int buf = 0;
        for (int k0 = 0; k0 < DD; k0 += 16) {
            double* as = As[buf];
            float*  bs = Bs[buf];
            {   // duplicated A store: each a value packed twice into one double
                unsigned u; unsigned long long p;
                u = __float_as_uint(ra.x); p = ((unsigned long long)u << 32) | u;
                as[(ak + 0) * 66 + ar] = __longlong_as_double(p);
                u = __float_as_uint(ra.y); p = ((unsigned long long)u << 32) | u;
                as[(ak + 1) * 66 + ar] = __longlong_as_double(p);
                u = __float_as_uint(ra.z); p = ((unsigned long long)u << 32) | u;
                as[(ak + 2) * 66 + ar] = __longlong_as_double(p);
                u = __float_as_uint(ra.w); p = ((unsigned long long)u << 32) | u;
                as[(ak + 3) * 66 + ar] = __longlong_as_double(p);
            }
            if (iscorr) {   // transposed scalar stores (rows of bag -> k-major)
                bs[(ckg * 4 + 0) * 128 + cj] = rb0.x;
                bs[(ckg * 4 + 1) * 128 + cj] = rb0.y;
                bs[(ckg * 4 + 2) * 128 + cj] = rb0.z;
                bs[(ckg * 4 + 3) * 128 + cj] = rb0.w;
                bs[(ckg * 4 + 8) * 128 + cj] = rb1.x;
                bs[(ckg * 4 + 9) * 128 + cj] = rb1.y;
                bs[(ckg * 4 + 10) * 128 + cj] = rb1.z;
                bs[(ckg * 4 + 11) * 128 + cj] = rb1.w;
            } else {
                *(float4*)&bs[bkr * 128 + bn] = rb0;
                *(float4*)&bs[(bkr + 8) * 128 + bn] = rb1;
            }
            __syncthreads();

            if (k0 + 16 < DD) {   // prefetch next k-tile under compute
                ra = *(const float4*)(Ab + (size_t)ar * DD + ak + k0 + 16);
                if (iscorr) {
                    rb0 = *(const float4*)(Bb + (size_t)cj * DD + ckg * 4 + k0 + 16);
                    rb1 = *(const float4*)(Bb + (size_t)cj * DD + ckg * 4 + 8 + k0 + 16);
                } else {
                    rb0 = *(const float4*)(Bb + (size_t)(k0 + 16 + bkr) * DD + n0 + bn);
                    rb1 = *(const float4*)(Bb + (size_t)(k0 + 16 + bkr + 8) * DD + n0 + bn);
                }
            }

#pragma unroll
            for (int k = 0; k < 16; k++) {
                double2 a01 = *(const double2*)&as[k * 66 + ty * 4];
                double2 a23 = *(const double2*)&as[k * 66 + ty * 4 + 2];
                double2 b01 = *(const double2*)&bs[k * 128 + tx * 8];
                double2 b23 = *(const double2*)&bs[k * 128 + tx * 8 + 4];
                unsigned long long ap[4] = {D2L(a01.x), D2L(a01.y), D2L(a23.x), D2L(a23.y)};
                unsigned long long bp[4] = {D2L(b01.x), D2L(b01.y), D2L(b23.x), D2L(b23.y)};
#pragma unroll
                for (int i = 0; i < 4; i++)
#pragma unroll
                    for (int j = 0; j < 4; j++) FMA2(acc[i][j], ap[i], bp[j]);
            }
            if (iscorr) {   // col-norm partial: thread half ckg covers 8 k's of col cj
#pragma unroll
                for (int kk = 0; kk < 8; kk++) {
                    float x = bs[(ckg * 8 + kk) * 128 + cj];
                    np = fmaf(x, x, np);
                }
            }
            buf ^= 1;
        }

        if (iscorr) {
            ss_part[ckg][cj] = np;
            __syncthreads();
            if (tid < 128) ninv_s[tid] = 1.0f / sqrtf(ss_part[0][tid] + ss_part[1][tid]);
            __syncthreads();
            float nj[8];
#pragma unroll
            for (int j = 0; j < 8; j++) nj[j] = ninv_s[tx * 8 + j];
            float* cg = g_corr + ((size_t)g * BAG + h * 64) * BAG;
#pragma unroll
            for (int i = 0; i < 4; i++) {
                int r = ty * 4 + i;
                float ni = ninv_s[h * 64 + r];
                float o[8];
#pragma unroll
                for (int jp = 0; jp < 4; jp++) {
                    o[2 * jp]     = LOF(acc[i][jp]);
                    o[2 * jp + 1] = HIF(acc[i][jp]);
                }
                float4 v0 = make_float4(o[0] * ni * nj[0], o[1] * ni * nj[1],
                                        o[2] * ni * nj[2], o[3] * ni * nj[3]);
                float4 v1 = make_float4(o[4] * ni * nj[4], o[5] * ni * nj[5],
                                        o[6] * ni * nj[6], o[7] * ni * nj[7]);
                *(float4*)&cg[(size_t)r * BAG + tx * 8]     = v0;
                *(float4*)&cg[(size_t)r * BAG + tx * 8 + 4] = v1;
            }
        } else {
#pragma unroll
            for (int i = 0; i < 4; i++) {
                int m = m0 + ty * 4 + i;
                float o[8];
#pragma unroll
                for (int jp = 0; jp < 4; jp++) {
                    o[2 * jp]     = LOF(acc[i][jp]);
                    o[2 * jp + 1] = HIF(acc[i][jp]);
                }
                *(float4*)&g_xw[(size_t)m * DD + n0 + tx * 8] =
                    make_float4(o[0], o[1], o[2], o[3]);
                *(float4*)&g_xw[(size_t)m * DD + n0 + tx * 8 + 4] =
                    make_float4(o[4], o[5], o[6], o[7]);
            }
        }
    }
}

// ---------------------------------------------------------------------------
// Kernel B1: per-bag top-16 via REDUX warp reductions (exact semantics:
// bit-exact max, lowest-index tie-break). Writes kept adj values, per-row
// GCN weight w_i = dis_i * sum_{j kept} dis_j into g_w.
// ---------------------------------------------------------------------------
__global__ __launch_bounds__(1024) void topk_kernel(float* __restrict__ adj) {
    __shared__ int      deg_s[128];
    __shared__ unsigned rm_s[128][4];
    __shared__ float    dis_s[128];
    int g = blockIdx.x, tid = threadIdx.x;
    int warp = tid >> 5, lane = tid & 31;
    if (tid < 128) deg_s[tid] = 0;
    __syncthreads();

    int degloc[4] = {0, 0, 0, 0};
    for (int rr = 0; rr < 4; rr++) {
        int i = warp * 4 + rr;
        const float* row = g_corr + ((size_t)g * BAG + i) * BAG;
        float v[4]; unsigned key[4];
#pragma unroll
        for (int q = 0; q < 4; q++) {
            v[q] = row[lane + 32 * q];
            unsigned b = __float_as_uint(v[q]);
            key[q] = (b & 0x80000000u) ? ~b : (b | 0x80000000u); // order-preserving
        }
        unsigned rm[4] = {0, 0, 0, 0};

        for (int t = 0; t < TOPK; t++) {
            unsigned m = max(max(key[0], key[1]), max(key[2], key[3]));
            unsigned wmax = __reduce_max_sync(0xffffffffu, m);
            if (wmax <= 0x80000000u) break;   // value <= 0: zeros win in reference
            unsigned my = 0xffffffffu;
#pragma unroll
            for (int q = 0; q < 4; q++)
                if (key[q] == wmax) my = min(my, (unsigned)(q * 32 + lane));
            int idx = (int)__reduce_min_sync(0xffffffffu, my);  // lowest index
            int q = idx >> 5;
            rm[q] |= 1u << (idx & 31);
            if ((idx & 31) == lane) {
                adj[((size_t)(g * BAG + i)) * NN + g * BAG + idx] = v[q];
                degloc[q]++;
                key[q] = 0;
            }
        }
        if (lane == 0) {
            rm_s[i][0] = rm[0]; rm_s[i][1] = rm[1];
            rm_s[i][2] = rm[2]; rm_s[i][3] = rm[3];
        }
    }
#pragma unroll
    for (int q = 0; q < 4; q++)
        if (degloc[q]) atomicAdd(&deg_s[q * 32 + lane], degloc[q]);
    __syncthreads();
    if (tid < 128) dis_s[tid] = 1.0f / sqrtf((float)deg_s[tid]);
    __syncthreads();
    if (tid < 128) {
        float s = 0.f;
#pragma unroll
        for (int q = 0; q < 4; q++) {
            unsigned m = rm_s[tid][q];
            while (m) { int j = __ffs(m) - 1; s += dis_s[q * 32 + j]; m &= m - 1; }
        }
        g_w[g * BAG + tid] = dis_s[tid] * s;
    }
}

// ---------------------------------------------------------------------------
// Kernel B2: agg[g,d] = sum_i w_i * xw[g*128+i, d] + 128*b[d].
// grid (64 bags, 4 col-chunks) x 256 threads (2 row-halves per col).
// ---------------------------------------------------------------------------
__global__ __launch_bounds__(256) void gcn_kernel(const float* __restrict__ b,
                                                  float* __restrict__ agg) {
    __shared__ float ws[128];
    __shared__ float part[128];
    int g = blockIdx.x, c = blockIdx.y, tid = threadIdx.x;
    if (tid < 128) ws[tid] = g_w[g * BAG + tid];
    __syncthreads();
    int col = c * 128 + (tid & 127);
    int half = tid >> 7;
    const float* xwb = g_xw + ((size_t)g * BAG + half * 64) * DD + col;
    float a = 0.f;
#pragma unroll 8
    for (int i = 0; i < 64; i++)
        a = fmaf(ws[half * 64 + i], xwb[(size_t)i * DD], a);
    if (half) part[tid & 127] = a;
    __syncthreads();
    if (!half) agg[g * DD + col] = a + part[tid & 127] + 128.0f * b[col];
}

// ---------------------------------------------------------------------------
extern "C" void kernel_launch(void* const* d_in, const int* in_sizes, int n_in,
                              void* d_out, int out_size) {
    (void)in_sizes; (void)n_in;
    const float* features = (const float*)d_in[0];
    const float* W        = (const float*)d_in[1];
    const float* b        = (const float*)d_in[2];

    float* out = (float*)d_out;
    float* agg = out;                                        // [64, 512]
    float* adj = out + ((size_t)out_size - (size_t)NN * NN); // [8192, 8192]

    void* ctrp = nullptr;
    cudaGetSymbolAddress(&ctrp, g_jobctr);
    cudaMemsetAsync(ctrp, 0, sizeof(int), 0);                // reset job counter

    fused_A<<<GRID_A, 256>>>(features, W, (float4*)d_out, out_size / 4);
    topk_kernel<<<NBAGS, 1024>>>(adj);
    gcn_kernel<<<dim3(NBAGS, 4), 256>>>(b, agg);
}

// round 11
// speedup vs baseline: 1.7411x; 1.7411x over previous
#include <cuda_runtime.h>
#include <math.h>
#include <stdint.h>

#define NN    8192
#define DD    512
#define NBAGS 64
#define BAG   128
#define TOPK  16

#define CJOBS  256      // corr jobs: (bag, quarter) 32x128 tiles
#define GRID_A 296      // 148 SMs x 2 CTAs
#define CHUNK4 65536    // float4 zeros per corr job (256/thread)

// ---- scratch (static device globals: no allocation at runtime) ----
static __device__ float g_ninv[NN];                // 1/||f_i||
static __device__ float g_corr[NBAGS * BAG * BAG]; // per-bag cosine blocks (4 MB)
static __device__ int   g_jobctr;                  // dynamic job counter

// ---------------------------------------------------------------------------
// 1) row norms. One thread per row, single k-ascending fma chain — bit-
//    identical to the R5 diagonal-accumulator chain (protects topk choices).
// ---------------------------------------------------------------------------
__global__ __launch_bounds__(256) void norms_kernel(const float* __restrict__ F) {
    int row = blockIdx.x * 256 + threadIdx.x;
    const float4* fr = (const float4*)(F + (size_t)row * DD);
    float ss = 0.f;
#pragma unroll 16
    for (int q = 0; q < 128; q++) {
        float4 v = fr[q];
        ss = fmaf(v.x, v.x, ss); ss = fmaf(v.y, v.y, ss);
        ss = fmaf(v.z, v.z, ss); ss = fmaf(v.w, v.w, ss);
    }
    g_ninv[row] = 1.0f / sqrtf(ss);
}

// ---------------------------------------------------------------------------
// 2) fused_A: 256 work-stolen corr quarter-tiles (32 rows x 128 cols, K=512),
//    with the 268 MB output zero-fill interleaved into the k-loop (8 STG.128
//    per thread per k-tile -> writes drain under the FMA-bound compute).
//    Jobless / finished blocks zero the tail.
// ---------------------------------------------------------------------------
__global__ __launch_bounds__(256, 2) void fused_A(const float* __restrict__ F,
                                                  float4* __restrict__ outz,
                                                  int total4) {
    __shared__ float Cs[2][16 * 132];   // k-major 128-row tile, padded
    __shared__ float ninv_s[128];
    __shared__ int   job_s;
    int tid = threadIdx.x;
    int tx = tid & 15, ty = tid >> 4;   // math: 2 rows x 8 cols per thread
    int r = tid & 127, h = tid >> 7;    // staging: row, k-half

    const float4 z4 = make_float4(0.f, 0.f, 0.f, 0.f);

    for (;;) {
        __syncthreads();                 // protect smem reuse across jobs
        if (tid == 0) job_s = atomicAdd(&g_jobctr, 1);
        __syncthreads();
        int job = job_s;
        if (job >= CJOBS) break;

        int g = job >> 2, q = job & 3;   // bag, row-quarter
        const float* fb = F + (size_t)g * BAG * DD;
        if (tid < 128) ninv_s[tid] = g_ninv[g * BAG + tid];

        float acc[2][8];
#pragma unroll
        for (int i = 0; i < 2; i++)
#pragma unroll
            for (int j = 0; j < 8; j++) acc[i][j] = 0.f;

        size_t zbase = (size_t)job * CHUNK4 + tid;

        // prefetch k-tile 0 (whole bag's 128 rows, 16 k's)
        float4 rb0 = *(const float4*)(fb + (size_t)r * DD + h * 8);
        float4 rb1 = *(const float4*)(fb + (size_t)r * DD + h * 8 + 4);

        int buf = 0;
        for (int k0 = 0; k0 < DD; k0 += 16) {
            float* cs = Cs[buf];
            cs[(h * 8 + 0) * 132 + r] = rb0.x;
            cs[(h * 8 + 1) * 132 + r] = rb0.y;
            cs[(h * 8 + 2) * 132 + r] = rb0.z;
            cs[(h * 8 + 3) * 132 + r] = rb0.w;
            cs[(h * 8 + 4) * 132 + r] = rb1.x;
            cs[(h * 8 + 5) * 132 + r] = rb1.y;
            cs[(h * 8 + 6) * 132 + r] = rb1.z;
            cs[(h * 8 + 7) * 132 + r] = rb1.w;
            __syncthreads();

            if (k0 + 16 < DD) {          // prefetch next k-tile under compute
                rb0 = *(const float4*)(fb + (size_t)r * DD + k0 + 16 + h * 8);
                rb1 = *(const float4*)(fb + (size_t)r * DD + k0 + 16 + h * 8 + 4);
            }

            // interleaved zero-fill: 8 fire-and-forget STG.128 per thread
            {
                size_t p = zbase + (size_t)(k0 >> 4) * 8 * 256;
#pragma unroll
                for (int s = 0; s < 8; s++) outz[p + (size_t)s * 256] = z4;
            }

#pragma unroll
            for (int k = 0; k < 16; k++) {
                float a0 = cs[k * 132 + q * 32 + ty * 2];
                float a1 = cs[k * 132 + q * 32 + ty * 2 + 1];
                float4 b0 = *(const float4*)&cs[k * 132 + tx * 8];
                float4 b1 = *(const float4*)&cs[k * 132 + tx * 8 + 4];
                float b[8] = {b0.x, b0.y, b0.z, b0.w, b1.x, b1.y, b1.z, b1.w};
#pragma unroll
                for (int j = 0; j < 8; j++) {
                    acc[0][j] = fmaf(a0, b[j], acc[0][j]);
                    acc[1][j] = fmaf(a1, b[j], acc[1][j]);
                }
            }
            buf ^= 1;
        }

        // epilogue: normalize and store this quarter's rows
        float nj[8];
#pragma unroll
        for (int j = 0; j < 8; j++) nj[j] = ninv_s[tx * 8 + j];
        float* cg = g_corr + ((size_t)g * BAG + q * 32) * BAG;
#pragma unroll
        for (int i = 0; i < 2; i++) {
            int rr = ty * 2 + i;
            float ni = ninv_s[q * 32 + rr];
            float4 v0 = make_float4(acc[i][0] * ni * nj[0], acc[i][1] * ni * nj[1],
                                    acc[i][2] * ni * nj[2], acc[i][3] * ni * nj[3]);
            float4 v1 = make_float4(acc[i][4] * ni * nj[4], acc[i][5] * ni * nj[5],
                                    acc[i][6] * ni * nj[6], acc[i][7] * ni * nj[7]);
            *(float4*)&cg[(size_t)rr * BAG + tx * 8]     = v0;
            *(float4*)&cg[(size_t)rr * BAG + tx * 8 + 4] = v1;
        }
    }

    // tail of the zero-fill not covered by job chunks
    for (size_t i = (size_t)CJOBS * CHUNK4 + (size_t)blockIdx.x * 256 + tid;
         i < (size_t)total4; i += (size_t)GRID_A * 256)
        outz[i] = z4;
}

// ---------------------------------------------------------------------------
// 3) fused_B: per bag — top-16 (R5-proven shfl argmax, lowest-index ties),
//    adj scatter, degrees -> w_i = dis_i * sum_{j kept} dis_j, then
//    y = sum_i w_i * F[i,:]  and  agg = y @ W + 128*b  (xw GEMM eliminated).
// ---------------------------------------------------------------------------
__global__ __launch_bounds__(1024) void fused_B(const float* __restrict__ F,
                                                const float* __restrict__ W,
                                                const float* __restrict__ bias,
                                                float* __restrict__ agg,
                                                float* __restrict__ adj) {
    __shared__ int      deg_s[128];
    __shared__ unsigned rm_s[128][4];
    __shared__ float    dis_s[128];
    __shared__ float    w_s[128];
    __shared__ float    y_s[512];
    __shared__ float    part_s[512];
    int g = blockIdx.x, tid = threadIdx.x;
    int warp = tid >> 5, lane = tid & 31;
    if (tid < 128) deg_s[tid] = 0;
    __syncthreads();

    // ---- phase 1: top-16 per row (32 warps x 4 rows) ----
    for (int rr = 0; rr < 4; rr++) {
        int i = warp * 4 + rr;
        const float* row = g_corr + ((size_t)g * BAG + i) * BAG;
        float v0 = row[lane], v1 = row[lane + 32], v2 = row[lane + 64], v3 = row[lane + 96];
        unsigned rm0 = 0, rm1 = 0, rm2 = 0, rm3 = 0;

        for (int t = 0; t < TOPK; t++) {
            float bv = v0; int bidx = lane;
            if (v1 > bv) { bv = v1; bidx = lane + 32; }
            if (v2 > bv) { bv = v2; bidx = lane + 64; }
            if (v3 > bv) { bv = v3; bidx = lane + 96; }
#pragma unroll
            for (int o = 16; o > 0; o >>= 1) {
                float ov = __shfl_xor_sync(0xffffffffu, bv, o);
                int   oi = __shfl_xor_sync(0xffffffffu, bidx, o);
                if (ov > bv || (ov == bv && oi < bidx)) { bv = ov; bidx = oi; }
            }
            if (bv <= 0.0f) break;  // remaining in-bag values lose to out-of-bag zeros
            if ((bidx & 31) == lane) {   // clear the winner
                int qq = bidx >> 5;
                if (qq == 0) v0 = -3e38f; else if (qq == 1) v1 = -3e38f;
                else if (qq == 2) v2 = -3e38f; else v3 = -3e38f;
            }
            int qq = bidx >> 5; unsigned bit = 1u << (bidx & 31);
            rm0 |= (qq == 0) ? bit : 0u; rm1 |= (qq == 1) ? bit : 0u;
            rm2 |= (qq == 2) ? bit : 0u; rm3 |= (qq == 3) ? bit : 0u;
            if (lane == 0) {
                adj[((size_t)(g * BAG + i)) * NN + g * BAG + bidx] = bv;
                atomicAdd(&deg_s[bidx], 1);
            }
        }
        if (lane == 0) {
            rm_s[i][0] = rm0; rm_s[i][1] = rm1; rm_s[i][2] = rm2; rm_s[i][3] = rm3;
        }
    }
    __syncthreads();
    if (tid < 128) dis_s[tid] = 1.0f / sqrtf((float)deg_s[tid]);
    __syncthreads();
    if (tid < 128) {
        float s = 0.f;
#pragma unroll
        for (int q = 0; q < 4; q++) {
            unsigned m = rm_s[tid][q];
            while (m) { int j = __ffs(m) - 1; s += dis_s[q * 32 + j]; m &= m - 1; }
        }
        w_s[tid] = dis_s[tid] * s;
    }
    __syncthreads();

    // ---- phase 2: y[d] = sum_i w_i * F[g*128+i, d] ----
    int col = tid & 511, half = tid >> 9;
    {
        const float* fb = F + ((size_t)g * BAG + half * 64) * DD + col;
        float a0 = 0.f, a1 = 0.f;
#pragma unroll 8
        for (int i = 0; i < 64; i += 2) {
            a0 = fmaf(w_s[half * 64 + i],     fb[(size_t)i * DD],       a0);
            a1 = fmaf(w_s[half * 64 + i + 1], fb[(size_t)(i + 1) * DD], a1);
        }
        if (half) part_s[col] = a0 + a1;
        __syncthreads();
        if (!half) y_s[col] = (a0 + a1) + part_s[col];
        __syncthreads();
    }

    // ---- phase 3: agg[n] = sum_k y[k] * W[k,n] + 128*b[n] ----
    {
        const float* wp = W + (size_t)half * 256 * DD + col;
        float s0 = 0.f, s1 = 0.f, s2 = 0.f, s3 = 0.f;
#pragma unroll 8
        for (int k = 0; k < 256; k += 4) {
            s0 = fmaf(y_s[half * 256 + k],     wp[(size_t)k * DD],       s0);
            s1 = fmaf(y_s[half * 256 + k + 1], wp[(size_t)(k + 1) * DD], s1);
            s2 = fmaf(y_s[half * 256 + k + 2], wp[(size_t)(k + 2) * DD], s2);
            s3 = fmaf(y_s[half * 256 + k + 3], wp[(size_t)(k + 3) * DD], s3);
        }
        float s = (s0 + s1) + (s2 + s3);
        if (half) part_s[col] = s;
        __syncthreads();
        if (!half) agg[g * DD + col] = s + part_s[col] + 128.0f * bias[col];
    }
}

// ---------------------------------------------------------------------------
extern "C" void kernel_launch(void* const* d_in, const int* in_sizes, int n_in,
                              void* d_out, int out_size) {
    (void)in_sizes; (void)n_in;
    const float* features = (const float*)d_in[0];
    const float* W        = (const float*)d_in[1];
    const float* b        = (const float*)d_in[2];

    float* out = (float*)d_out;
    float* agg = out;                                        // [64, 512]
    float* adj = out + ((size_t)out_size - (size_t)NN * NN); // [8192, 8192]

    void* ctrp = nullptr;
    cudaGetSymbolAddress(&ctrp, g_jobctr);
    cudaMemsetAsync(ctrp, 0, sizeof(int), 0);                // reset job counter

    norms_kernel<<<NN / 256, 256>>>(features);
    fused_A<<<GRID_A, 256>>>(features, (float4*)d_out, out_size / 4);
    fused_B<<<NBAGS, 1024>>>(features, W, b, agg, adj);
}